// round 8
// baseline (speedup 1.0000x reference)
#include <cuda_runtime.h>
#include <cuda_bf16.h>
#include <cstdint>
#include <math.h>

// ---------------- problem constants ----------------
#define NB 2
#define NS 1024
#define ND 1024
#define NH 16
#define NDH 64
#define NL 4
#define NDFF 4096
#define NV 32000
#define NR 2047              // 2*MAXLEN-1
#define NROWS (NB*NS)        // 2048

// ---------------- scratch (static device allocations) ----------------
__device__ float g_x[NROWS*ND];
__device__ float g_q[NROWS*ND];
__device__ float g_k[NROWS*ND];
__device__ float g_v[NROWS*ND];
__device__ float g_t[NROWS*ND];
__device__ float g_p[2*NROWS*ND];             // split-K partials
__device__ float g_qr[(size_t)NROWS*NH*NR];   // [B*S*H, 2047]

// split-bf16 activation buffers (hi/lo)
__device__ __nv_bfloat16 g_xh[NROWS*ND],  g_xl[NROWS*ND];
__device__ __nv_bfloat16 g_qh[NROWS*ND],  g_ql[NROWS*ND];
__device__ __nv_bfloat16 g_oh[NROWS*ND],  g_ol[NROWS*ND];
__device__ __nv_bfloat16 g_hh[NROWS*NDFF], g_hl[NROWS*NDFF];
// weight split buffers
__device__ __nv_bfloat16 g_Bh[(size_t)NV*ND];
__device__ __nv_bfloat16 g_Bl[(size_t)NV*ND];

// ---------------- helpers ----------------
__device__ __forceinline__ uint32_t smem_u32(const void* p) {
    uint32_t a;
    asm("{ .reg .u64 t; cvta.to.shared.u64 t, %1; cvt.u32.u64 %0, t; }" : "=r"(a) : "l"(p));
    return a;
}

#define LDSM4(r, a) \
    asm volatile("ldmatrix.sync.aligned.m8n8.x4.shared.b16 {%0,%1,%2,%3}, [%4];" \
        : "=r"((r)[0]), "=r"((r)[1]), "=r"((r)[2]), "=r"((r)[3]) : "r"(a))

#define MMA16816(d, a, b) \
    asm volatile("mma.sync.aligned.m16n8k16.row.col.f32.bf16.bf16.f32 " \
        "{%0,%1,%2,%3}, {%4,%5,%6,%7}, {%8,%9}, {%0,%1,%2,%3};" \
        : "+f"((d)[0]), "+f"((d)[1]), "+f"((d)[2]), "+f"((d)[3]) \
        : "r"((a)[0]), "r"((a)[1]), "r"((a)[2]), "r"((a)[3]), "r"((b)[0]), "r"((b)[1]))

#define CP_ASYNC16(dst, src, sz) \
    asm volatile("cp.async.cg.shared.global [%0], [%1], 16, %2;" \
        :: "r"(dst), "l"(src), "r"(sz))
#define CP_COMMIT() asm volatile("cp.async.commit_group;")
#define CP_WAIT0()  asm volatile("cp.async.wait_group 0;")
#define CP_WAIT1()  asm volatile("cp.async.wait_group 1;")

__device__ __forceinline__ void split2(float v0, float v1,
                                       __nv_bfloat16* hi, __nv_bfloat16* lo) {
    __nv_bfloat16 h0 = __float2bfloat16(v0);
    __nv_bfloat16 h1 = __float2bfloat16(v1);
    __nv_bfloat16 l0 = __float2bfloat16(v0 - __bfloat162float(h0));
    __nv_bfloat16 l1 = __float2bfloat16(v1 - __bfloat162float(h1));
    *reinterpret_cast<__nv_bfloat162*>(hi) = __nv_bfloat162(h0, h1);
    *reinterpret_cast<__nv_bfloat162*>(lo) = __nv_bfloat162(l0, l1);
}

// ---------------- fp32 -> bf16 hi/lo split (weights) ----------------
__global__ void split_kernel(const float4* __restrict__ src,
                             __nv_bfloat16* __restrict__ hi,
                             __nv_bfloat16* __restrict__ lo, int n4) {
    int i = blockIdx.x * 256 + threadIdx.x;
    if (i >= n4) return;
    float4 v = src[i];
    split2(v.x, v.y, hi + i*4,     lo + i*4);
    split2(v.z, v.w, hi + i*4 + 2, lo + i*4 + 2);
}

// ---------------- embedding: x = emb[tgt]*32, also emit hi/lo ----------------
__global__ void embed_kernel(const int* __restrict__ tgt,
                             const float* __restrict__ emb,
                             float* __restrict__ x,
                             __nv_bfloat16* __restrict__ xh,
                             __nv_bfloat16* __restrict__ xl) {
    int idx = blockIdx.x * blockDim.x + threadIdx.x;
    int row = idx >> 8;
    int c4  = idx & 255;
    float4 v = reinterpret_cast<const float4*>(emb + (size_t)tgt[row] * ND)[c4];
    v.x *= 32.f; v.y *= 32.f; v.z *= 32.f; v.w *= 32.f;
    reinterpret_cast<float4*>(x)[idx] = v;
    split2(v.x, v.y, xh + idx*4,     xl + idx*4);
    split2(v.z, v.w, xh + idx*4 + 2, xl + idx*4 + 2);
}

// ---------------- split-K reduce: out = relu(alpha*(P0+P1+bias)), opt hi/lo ----------------
__global__ __launch_bounds__(256) void reduce2_kernel(
    float* __restrict__ out, __nv_bfloat16* __restrict__ oh, __nv_bfloat16* __restrict__ ol,
    const float* __restrict__ P, const float* __restrict__ bias,
    int N, int total4, float alpha, int relu)
{
    int idx = blockIdx.x * 256 + threadIdx.x;
    if (idx >= total4) return;
    const float4* P0 = reinterpret_cast<const float4*>(P);
    const float4* P1 = P0 + total4;
    float4 a = P0[idx], b = P1[idx];
    int col = (idx << 2) & (N - 1);          // N is a power of two here
    float4 bz = *reinterpret_cast<const float4*>(bias + col);
    float4 o;
    o.x = (a.x + b.x + bz.x) * alpha;
    o.y = (a.y + b.y + bz.y) * alpha;
    o.z = (a.z + b.z + bz.z) * alpha;
    o.w = (a.w + b.w + bz.w) * alpha;
    if (relu) {
        o.x = fmaxf(o.x, 0.f); o.y = fmaxf(o.y, 0.f);
        o.z = fmaxf(o.z, 0.f); o.w = fmaxf(o.w, 0.f);
    }
    reinterpret_cast<float4*>(out)[idx] = o;
    if (oh) {
        split2(o.x, o.y, oh + idx*4,     ol + idx*4);
        split2(o.z, o.w, oh + idx*4 + 2, ol + idx*4 + 2);
    }
}

// ---------------- split-bf16 tensor-core GEMM (mma.sync) ----------------
// 4 warps (128 threads), warp tile 64x64 on a 128x128 CTA tile, k-tile 32,
// 3-stage cp.async pipeline. Minimizes smem-crossbar traffic: A and B
// fragments are each re-read by only 2 warps (was 4x/2x with 8 warps).
#define STG 32768
#define TOFF 8192
#define GEMM_SMEM (3*STG)

__device__ __forceinline__ void ld_tile_async(
    uint32_t sbase, const __nv_bfloat16* __restrict__ g,
    int ldk, int row0, int k0, int rmax, int tid)
{
    #pragma unroll
    for (int it = 0; it < 4; it++) {
        int qq = tid + it * 128;
        int r = qq >> 2, c = qq & 3;
        uint32_t dst = sbase + r * 64 + ((c ^ ((r >> 1) & 3)) << 4);
        int rr = (r < rmax) ? r : 0;
        const __nv_bfloat16* src = g + (size_t)(row0 + rr) * ldk + k0 + c * 8;
        int sz = (r < rmax) ? 16 : 0;
        CP_ASYNC16(dst, src, sz);
    }
}

__device__ __forceinline__ void ld_stage(
    uint32_t sbase, const __nv_bfloat16* Ah, const __nv_bfloat16* Al,
    const __nv_bfloat16* Bh, const __nv_bfloat16* Bl,
    int ldk, int m0, int n0, int k0, int bn, int tid, int terms)
{
    ld_tile_async(sbase + 0*TOFF, Ah, ldk, m0, k0, 128, tid);
    ld_tile_async(sbase + 2*TOFF, Bh, ldk, n0, k0, bn, tid);
    if (terms == 3) {
        ld_tile_async(sbase + 1*TOFF, Al, ldk, m0, k0, 128, tid);
        ld_tile_async(sbase + 3*TOFF, Bl, ldk, n0, k0, bn, tid);
    }
}

__global__ __launch_bounds__(128, 2) void gemm_tc(
    float* __restrict__ C, __nv_bfloat16* __restrict__ Ch, __nv_bfloat16* __restrict__ Cl,
    const __nv_bfloat16* __restrict__ Ah, const __nv_bfloat16* __restrict__ Al,
    const __nv_bfloat16* __restrict__ Bh, const __nv_bfloat16* __restrict__ Bl,
    const float* __restrict__ bias, int M, int N, int K, int ldk,
    float alpha, int relu, int terms)
{
    extern __shared__ char sm[];
    uint32_t smb = smem_u32(sm);
    int tid = threadIdx.x;
    int wid = tid >> 5;
    int lane = tid & 31;
    int wm = wid & 1;          // 2 warps along M
    int wn = wid >> 1;         // 2 warps along N
    int m0 = blockIdx.y * 128;
    int n0 = blockIdx.x * 128;
    int kbase = blockIdx.z * K;
    if (C) C += (size_t)blockIdx.z * M * N;
    int NT = K >> 5;
    int bn = N - n0; if (bn > 128) bn = 128;

    ld_stage(smb, Ah, Al, Bh, Bl, ldk, m0, n0, kbase, bn, tid, terms);
    CP_COMMIT();
    if (NT > 1) {
        ld_stage(smb + STG, Ah, Al, Bh, Bl, ldk, m0, n0, kbase + 32, bn, tid, terms);
        CP_COMMIT();
    }

    float acc[4][8][4];
    #pragma unroll
    for (int i = 0; i < 4; i++)
        #pragma unroll
        for (int j = 0; j < 8; j++)
            #pragma unroll
            for (int e = 0; e < 4; e++) acc[i][j][e] = 0.f;

    int slot = 0, pslot = 2;
    for (int kt = 0; kt < NT; kt++) {
        if (kt + 1 < NT) { CP_WAIT1(); } else { CP_WAIT0(); }
        __syncthreads();

        if (kt + 2 < NT) {
            ld_stage(smb + pslot * STG, Ah, Al, Bh, Bl, ldk, m0, n0,
                     kbase + ((kt + 2) << 5), bn, tid, terms);
            CP_COMMIT();
        }

        uint32_t sA = smb + slot * STG;
        uint32_t sB = sA + 2*TOFF;

        #pragma unroll
        for (int ks = 0; ks < 2; ks++) {
            uint32_t ah[4][4], al[4][4], bh[8][2], bl[8][2];
            int cc = ks * 2 + (lane >> 4);
            #pragma unroll
            for (int mf = 0; mf < 4; mf++) {
                int row = wm * 64 + mf * 16 + (lane & 15);
                uint32_t ad = sA + row * 64 + (((cc ^ ((row >> 1) & 3))) << 4);
                LDSM4(ah[mf], ad);
                if (terms == 3) LDSM4(al[mf], ad + TOFF);
            }
            #pragma unroll
            for (int np = 0; np < 4; np++) {
                int rn = wn * 64 + np * 16 + (lane & 15);
                uint32_t bd = sB + rn * 64 + (((cc ^ ((rn >> 1) & 3))) << 4);
                uint32_t t4[4];
                LDSM4(t4, bd);
                bh[np*2][0] = t4[0]; bh[np*2][1] = t4[2];
                bh[np*2+1][0] = t4[1]; bh[np*2+1][1] = t4[3];
                if (terms == 3) {
                    LDSM4(t4, bd + TOFF);
                    bl[np*2][0] = t4[0]; bl[np*2][1] = t4[2];
                    bl[np*2+1][0] = t4[1]; bl[np*2+1][1] = t4[3];
                }
            }
            #pragma unroll
            for (int mf = 0; mf < 4; mf++)
                #pragma unroll
                for (int nf = 0; nf < 8; nf++)
                    MMA16816(acc[mf][nf], ah[mf], bh[nf]);
            if (terms == 3) {
                #pragma unroll
                for (int mf = 0; mf < 4; mf++)
                    #pragma unroll
                    for (int nf = 0; nf < 8; nf++)
                        MMA16816(acc[mf][nf], ah[mf], bl[nf]);
                #pragma unroll
                for (int mf = 0; mf < 4; mf++)
                    #pragma unroll
                    for (int nf = 0; nf < 8; nf++)
                        MMA16816(acc[mf][nf], al[mf], bh[nf]);
            }
        }
        slot = (slot == 2) ? 0 : slot + 1;
        pslot = (pslot == 2) ? 0 : pslot + 1;
    }

    // epilogue: warp covers rows wm*64..+64, cols wn*64..+64
    bool fast = ((N & 1) == 0) && (n0 + 128 <= N);
    #pragma unroll
    for (int mf = 0; mf < 4; mf++) {
        int r0 = m0 + wm * 64 + mf * 16 + (lane >> 2);
        #pragma unroll
        for (int half = 0; half < 2; half++) {
            int row = r0 + half * 8;
            size_t rbase = (size_t)row * N;
            #pragma unroll
            for (int nf = 0; nf < 8; nf++) {
                int col = n0 + wn * 64 + nf * 8 + (lane & 3) * 2;
                float v0 = acc[mf][nf][half * 2 + 0];
                float v1 = acc[mf][nf][half * 2 + 1];
                if (bias) { v0 += bias[col]; v1 += __ldg(&bias[col + 1]); }
                v0 *= alpha; v1 *= alpha;
                if (relu) { v0 = fmaxf(v0, 0.f); v1 = fmaxf(v1, 0.f); }
                if (fast) {
                    if (C) *reinterpret_cast<float2*>(C + rbase + col) = make_float2(v0, v1);
                    if (Ch) split2(v0, v1, Ch + rbase + col, Cl + rbase + col);
                } else {
                    if (C) {
                        if (col < N)     C[rbase + col] = v0;
                        if (col + 1 < N) C[rbase + col + 1] = v1;
                    }
                }
            }
        }
    }
}

// ---------------- fused attention (flash-style, exact softmax semantics) ----------------
#define QT 128
#define KT 64
#define LDQ 68

__global__ __launch_bounds__(128, 2) void attn_kernel(
    __nv_bfloat16* __restrict__ oh, __nv_bfloat16* __restrict__ ol,
    const float* __restrict__ q, const float* __restrict__ k,
    const float* __restrict__ v, const float* __restrict__ qr, const int* __restrict__ tgt)
{
    extern __shared__ float smf[];
    float* qs = smf;
    float* ks = qs + QT*LDQ;
    float* vs = ks + KT*LDQ;
    float* ps = vs + KT*LDQ;
    int*   pf = (int*)(ps + QT*LDQ);

    int b = blockIdx.z, h = blockIdx.y;
    int tid = threadIdx.x;
    int i0 = blockIdx.x * QT;
    int i  = i0 + tid;

    for (int t = tid; t < QT*NDH/4; t += 128) {
        int r  = t >> 4;
        int c4 = (t & 15) << 2;
        float4 va = *reinterpret_cast<const float4*>(
            &q[((size_t)(b*NS + i0 + r))*ND + h*NDH + c4]);
        *reinterpret_cast<float4*>(&qs[r*LDQ + c4]) = va;
    }

    float o[NDH];
    #pragma unroll
    for (int d = 0; d < NDH; d++) o[d] = 0.f;
    float m = -1e30f, l = 0.f;
    const float* qrrow = qr + ((size_t)((b*NS + i)*NH + h)) * NR + (1023 - i);

    int jend = (tgt[b*NS] == 0) ? NS : (i0 + QT);

    for (int j0 = 0; j0 < jend; j0 += KT) {
        __syncthreads();
        for (int t = tid; t < KT*NDH/4; t += 128) {
            int r  = t >> 4;
            int c4 = (t & 15) << 2;
            size_t g = ((size_t)(b*NS + j0 + r))*ND + h*NDH + c4;
            *reinterpret_cast<float4*>(&ks[r*LDQ + c4]) =
                *reinterpret_cast<const float4*>(&k[g]);
            *reinterpret_cast<float4*>(&vs[r*LDQ + c4]) =
                *reinterpret_cast<const float4*>(&v[g]);
        }
        if (tid < KT) pf[tid] = (tgt[b*NS + j0 + tid] == 0) ? 1 : 0;
        __syncthreads();

        float s[KT];
        #pragma unroll
        for (int j = 0; j < KT; j++) s[j] = 0.f;
        #pragma unroll 1
        for (int d = 0; d < NDH; d += 4) {
            float4 qd = *reinterpret_cast<const float4*>(&qs[tid*LDQ + d]);
            #pragma unroll
            for (int j = 0; j < KT; j++) {
                float4 kj = *reinterpret_cast<const float4*>(&ks[j*LDQ + d]);
                s[j] += qd.x*kj.x + qd.y*kj.y + qd.z*kj.z + qd.w*kj.w;
            }
        }
        float mt = m;
        #pragma unroll
        for (int j = 0; j < KT; j++) {
            int jj = j0 + j;
            float val = s[j] + qrrow[jj];
            if (jj > i || pf[j]) val = -1e9f;
            s[j] = val;
            mt = fmaxf(mt, val);
        }
        float corr = __expf(m - mt);
        m = mt;
        l *= corr;
        #pragma unroll
        for (int d = 0; d < NDH; d++) o[d] *= corr;
        #pragma unroll
        for (int j = 0; j < KT; j += 4) {
            float4 pv;
            pv.x = __expf(s[j]   - m);
            pv.y = __expf(s[j+1] - m);
            pv.z = __expf(s[j+2] - m);
            pv.w = __expf(s[j+3] - m);
            l += pv.x + pv.y + pv.z + pv.w;
            *reinterpret_cast<float4*>(&ps[tid*LDQ + j]) = pv;
        }
        #pragma unroll 1
        for (int j = 0; j < KT; j++) {
            float p = ps[tid*LDQ + j];
            #pragma unroll
            for (int d = 0; d < NDH; d += 4) {
                float4 vj = *reinterpret_cast<const float4*>(&vs[j*LDQ + d]);
                o[d]   += p*vj.x;
                o[d+1] += p*vj.y;
                o[d+2] += p*vj.z;
                o[d+3] += p*vj.w;
            }
        }
    }
    float inv = 1.f / l;
    size_t base = ((size_t)(b*NS + i))*ND + h*NDH;
    #pragma unroll
    for (int d = 0; d < NDH; d += 2)
        split2(o[d]*inv, o[d+1]*inv, oh + base + d, ol + base + d);
}

// ---------------- residual add + LayerNorm (in place on x, also emit hi/lo) ----------------
__global__ __launch_bounds__(256) void add_ln_kernel(
    float* __restrict__ x, __nv_bfloat16* __restrict__ xh, __nv_bfloat16* __restrict__ xl,
    const float* __restrict__ y,
    const float* __restrict__ gw, const float* __restrict__ bw)
{
    __shared__ float buf[ND];
    __shared__ float red[33];
    int row = blockIdx.x;
    int tid = threadIdx.x;
    size_t base = (size_t)row * ND;

    float s = 0.f;
    for (int d = tid; d < ND; d += 256) {
        float t = x[base + d] + y[base + d];
        buf[d] = t;
        s += t;
    }
    #pragma unroll
    for (int off = 16; off; off >>= 1) s += __shfl_xor_sync(0xffffffffu, s, off);
    if ((tid & 31) == 0) red[tid >> 5] = s;
    __syncthreads();
    if (tid < 32) {
        float v2 = (tid < 8) ? red[tid] : 0.f;
        #pragma unroll
        for (int off = 4; off; off >>= 1) v2 += __shfl_xor_sync(0xffffffffu, v2, off);
        if (tid == 0) red[32] = v2;
    }
    __syncthreads();
    float mean = red[32] * (1.f/ND);

    float sv = 0.f;
    for (int d = tid; d < ND; d += 256) {
        float t = buf[d] - mean;
        sv += t*t;
    }
    #pragma unroll
    for (int off = 16; off; off >>= 1) sv += __shfl_xor_sync(0xffffffffu, sv, off);
    __syncthreads();
    if ((tid & 31) == 0) red[tid >> 5] = sv;
    __syncthreads();
    if (tid < 32) {
        float v2 = (tid < 8) ? red[tid] : 0.f;
        #pragma unroll
        for (int off = 4; off; off >>= 1) v2 += __shfl_xor_sync(0xffffffffu, v2, off);
        if (tid == 0) red[32] = v2;
    }
    __syncthreads();
    float inv = rsqrtf(red[32] * (1.f/ND) + 1e-5f);
    for (int d = tid*2; d < ND; d += 512) {
        float v0 = (buf[d]   - mean) * inv * gw[d]   + bw[d];
        float v1 = (buf[d+1] - mean) * inv * gw[d+1] + bw[d+1];
        x[base + d]   = v0;
        x[base + d+1] = v1;
        split2(v0, v1, xh + base + d, xl + base + d);
    }
}

// ---------------- host orchestration ----------------
static inline void split(const float* src, __nv_bfloat16* hi, __nv_bfloat16* lo, size_t n) {
    int n4 = (int)(n / 4);
    split_kernel<<<(n4 + 255) / 256, 256>>>(
        reinterpret_cast<const float4*>(src), hi, lo, n4);
}

extern "C" void kernel_launch(void* const* d_in, const int* in_sizes, int n_in,
                              void* d_out, int out_size)
{
    (void)in_sizes; (void)n_in; (void)out_size;
    const int*   tgt = (const int*)d_in[0];
    const float* emb = (const float*)d_in[1];
    const float* Wq  = (const float*)d_in[2];
    const float* bq  = (const float*)d_in[3];
    const float* Wk  = (const float*)d_in[4];
    const float* bk  = (const float*)d_in[5];
    const float* Wv  = (const float*)d_in[6];
    const float* bv  = (const float*)d_in[7];
    const float* Wo  = (const float*)d_in[8];
    const float* bo  = (const float*)d_in[9];
    const float* rel = (const float*)d_in[10];
    const float* W1  = (const float*)d_in[11];
    const float* b1  = (const float*)d_in[12];
    const float* W2  = (const float*)d_in[13];
    const float* b2  = (const float*)d_in[14];
    const float* g1  = (const float*)d_in[15];
    const float* be1 = (const float*)d_in[16];
    const float* g2  = (const float*)d_in[17];
    const float* be2 = (const float*)d_in[18];
    const float* Wf  = (const float*)d_in[19];
    const float* bf  = (const float*)d_in[20];
    float* logits = (float*)d_out;

    float *x_, *q_, *k_, *v_, *t_, *p_, *qr_;
    __nv_bfloat16 *xh, *xl, *qh, *ql, *oh, *ol, *hh, *hl, *Bh, *Bl;
    cudaGetSymbolAddress((void**)&x_,  g_x);
    cudaGetSymbolAddress((void**)&q_,  g_q);
    cudaGetSymbolAddress((void**)&k_,  g_k);
    cudaGetSymbolAddress((void**)&v_,  g_v);
    cudaGetSymbolAddress((void**)&t_,  g_t);
    cudaGetSymbolAddress((void**)&p_,  g_p);
    cudaGetSymbolAddress((void**)&qr_, g_qr);
    cudaGetSymbolAddress((void**)&xh,  g_xh);
    cudaGetSymbolAddress((void**)&xl,  g_xl);
    cudaGetSymbolAddress((void**)&qh,  g_qh);
    cudaGetSymbolAddress((void**)&ql,  g_ql);
    cudaGetSymbolAddress((void**)&oh,  g_oh);
    cudaGetSymbolAddress((void**)&ol,  g_ol);
    cudaGetSymbolAddress((void**)&hh,  g_hh);
    cudaGetSymbolAddress((void**)&hl,  g_hl);
    cudaGetSymbolAddress((void**)&Bh,  g_Bh);
    cudaGetSymbolAddress((void**)&Bl,  g_Bl);

    int attn_smem = (QT*LDQ + KT*LDQ + KT*LDQ + QT*LDQ)*(int)sizeof(float) + KT*(int)sizeof(int);
    cudaFuncSetAttribute(attn_kernel, cudaFuncAttributeMaxDynamicSharedMemorySize, attn_smem);
    cudaFuncSetAttribute(gemm_tc, cudaFuncAttributeMaxDynamicSharedMemorySize, GEMM_SMEM);

    embed_kernel<<<NROWS*ND/4/256, 256>>>(tgt, emb, x_, xh, xl);

    const int RED4 = NROWS*ND/4;
    const dim3 gRED((RED4 + 255)/256);
    __nv_bfloat16* nb = nullptr;
    float* nf = nullptr;

    for (int l = 0; l < NL; l++) {
        const size_t WDD = (size_t)ND*ND;
        // q/k/v projections: split-K=2 (K=512 per slice, ldk=1024)
        split(Wq + l*WDD, Bh, Bl, WDD);
        gemm_tc<<<dim3(ND/128, NROWS/128, 2), 128, GEMM_SMEM>>>(
            p_, nb, nb, xh, xl, Bh, Bl, nf, NROWS, ND, 512, ND, 1.f, 0, 3);
        reduce2_kernel<<<gRED, 256>>>(q_, qh, ql, p_, bq + l*ND, ND, RED4, 0.125f, 0);
        split(Wk + l*WDD, Bh, Bl, WDD);
        gemm_tc<<<dim3(ND/128, NROWS/128, 2), 128, GEMM_SMEM>>>(
            p_, nb, nb, xh, xl, Bh, Bl, nf, NROWS, ND, 512, ND, 1.f, 0, 3);
        reduce2_kernel<<<gRED, 256>>>(k_, nb, nb, p_, bk + l*ND, ND, RED4, 1.f, 0);
        split(Wv + l*WDD, Bh, Bl, WDD);
        gemm_tc<<<dim3(ND/128, NROWS/128, 2), 128, GEMM_SMEM>>>(
            p_, nb, nb, xh, xl, Bh, Bl, nf, NROWS, ND, 512, ND, 1.f, 0, 3);
        reduce2_kernel<<<gRED, 256>>>(v_, nb, nb, p_, bv + l*ND, ND, RED4, 1.f, 0);

        // QR[bsh, r] = q . rel^T : M=32768, N=2047, K=64 — single-term bf16
        split(rel + (size_t)l*NR*NDH, Bh, Bl, (size_t)NR*NDH);
        gemm_tc<<<dim3((NR + 127)/128, NROWS*NH/128), 128, GEMM_SMEM>>>(
            qr_, nb, nb, qh, ql, Bh, Bl, nf, NROWS*NH, NR, NDH, NDH, 1.f, 0, 1);

        attn_kernel<<<dim3(NS/QT, NH, NB), 128, attn_smem>>>(oh, ol, q_, k_, v_, qr_, tgt);

        // output projection (split-K=2) + LN (emits xh/xl)
        split(Wo + l*WDD, Bh, Bl, WDD);
        gemm_tc<<<dim3(ND/128, NROWS/128, 2), 128, GEMM_SMEM>>>(
            p_, nb, nb, oh, ol, Bh, Bl, nf, NROWS, ND, 512, ND, 1.f, 0, 3);
        reduce2_kernel<<<gRED, 256>>>(t_, nb, nb, p_, bo + l*ND, ND, RED4, 1.f, 0);
        add_ln_kernel<<<NROWS, 256>>>(x_, xh, xl, t_, g1 + l*ND, be1 + l*ND);

        // FFN1: write h directly as bf16 hi/lo (no fp32 h)
        split(W1 + (size_t)l*NDFF*ND, Bh, Bl, (size_t)NDFF*ND);
        gemm_tc<<<dim3(NDFF/128, NROWS/128), 128, GEMM_SMEM>>>(
            nf, hh, hl, xh, xl, Bh, Bl, b1 + l*NDFF, NROWS, NDFF, ND, ND, 1.f, 1, 3);
        // FFN2 (K=4096 -> split-K=2 of 2048)
        split(W2 + (size_t)l*ND*NDFF, Bh, Bl, (size_t)ND*NDFF);
        gemm_tc<<<dim3(ND/128, NROWS/128, 2), 128, GEMM_SMEM>>>(
            p_, nb, nb, hh, hl, Bh, Bl, nf, NROWS, ND, 2048, NDFF, 1.f, 0, 3);
        reduce2_kernel<<<gRED, 256>>>(t_, nb, nb, p_, b2 + l*ND, ND, RED4, 1.f, 0);
        add_ln_kernel<<<NROWS, 256>>>(x_, xh, xl, t_, g2 + l*ND, be2 + l*ND);
    }

    // final logits: M=2048, N=32000, K=1024
    split(Wf, Bh, Bl, (size_t)NV*ND);
    gemm_tc<<<dim3(NV/128, NROWS/128), 128, GEMM_SMEM>>>(
        logits, nb, nb, xh, xl, Bh, Bl, bf, NROWS, NV, ND, ND, 1.f, 0, 3);
}

// round 9
// speedup vs baseline: 1.0099x; 1.0099x over previous
#include <cuda_runtime.h>
#include <cuda_bf16.h>
#include <cstdint>
#include <math.h>

// ---------------- problem constants ----------------
#define NB 2
#define NS 1024
#define ND 1024
#define NH 16
#define NDH 64
#define NL 4
#define NDFF 4096
#define NV 32000
#define NR 2047              // 2*MAXLEN-1
#define NROWS (NB*NS)        // 2048

// ---------------- scratch (static device allocations) ----------------
__device__ float g_x[NROWS*ND];
__device__ float g_q[NROWS*ND];
__device__ float g_k[NROWS*ND];
__device__ float g_v[NROWS*ND];
__device__ float g_t[NROWS*ND];
__device__ float g_p[2*NROWS*ND];                     // split-K partials
__device__ __nv_bfloat16 g_qrb[(size_t)NROWS*NH*NR];  // qr in bf16

// split-bf16 activation buffers (hi/lo)
__device__ __nv_bfloat16 g_xh[NROWS*ND],  g_xl[NROWS*ND];
__device__ __nv_bfloat16 g_qh[NROWS*ND],  g_ql[NROWS*ND];
__device__ __nv_bfloat16 g_oh[NROWS*ND],  g_ol[NROWS*ND];
__device__ __nv_bfloat16 g_hh[NROWS*NDFF], g_hl[NROWS*NDFF];
// weight split buffers
__device__ __nv_bfloat16 g_Bh[(size_t)NV*ND];
__device__ __nv_bfloat16 g_Bl[(size_t)NV*ND];

// ---------------- helpers ----------------
__device__ __forceinline__ uint32_t smem_u32(const void* p) {
    uint32_t a;
    asm("{ .reg .u64 t; cvta.to.shared.u64 t, %1; cvt.u32.u64 %0, t; }" : "=r"(a) : "l"(p));
    return a;
}

#define LDSM4(r, a) \
    asm volatile("ldmatrix.sync.aligned.m8n8.x4.shared.b16 {%0,%1,%2,%3}, [%4];" \
        : "=r"((r)[0]), "=r"((r)[1]), "=r"((r)[2]), "=r"((r)[3]) : "r"(a))
#define LDSM2(r, a) \
    asm volatile("ldmatrix.sync.aligned.m8n8.x2.shared.b16 {%0,%1}, [%2];" \
        : "=r"((r)[0]), "=r"((r)[1]) : "r"(a))

#define MMA16816(d, a, b) \
    asm volatile("mma.sync.aligned.m16n8k16.row.col.f32.bf16.bf16.f32 " \
        "{%0,%1,%2,%3}, {%4,%5,%6,%7}, {%8,%9}, {%0,%1,%2,%3};" \
        : "+f"((d)[0]), "+f"((d)[1]), "+f"((d)[2]), "+f"((d)[3]) \
        : "r"((a)[0]), "r"((a)[1]), "r"((a)[2]), "r"((a)[3]), "r"((b)[0]), "r"((b)[1]))

#define CP_ASYNC16(dst, src, sz) \
    asm volatile("cp.async.cg.shared.global [%0], [%1], 16, %2;" \
        :: "r"(dst), "l"(src), "r"(sz))
#define CP_COMMIT() asm volatile("cp.async.commit_group;")
#define CP_WAIT0()  asm volatile("cp.async.wait_group 0;")
#define CP_WAIT1()  asm volatile("cp.async.wait_group 1;")

__device__ __forceinline__ void split2(float v0, float v1,
                                       __nv_bfloat16* hi, __nv_bfloat16* lo) {
    __nv_bfloat16 h0 = __float2bfloat16(v0);
    __nv_bfloat16 h1 = __float2bfloat16(v1);
    __nv_bfloat16 l0 = __float2bfloat16(v0 - __bfloat162float(h0));
    __nv_bfloat16 l1 = __float2bfloat16(v1 - __bfloat162float(h1));
    *reinterpret_cast<__nv_bfloat162*>(hi) = __nv_bfloat162(h0, h1);
    *reinterpret_cast<__nv_bfloat162*>(lo) = __nv_bfloat162(l0, l1);
}

// ---------------- fp32 -> bf16 hi/lo split (weights) ----------------
__global__ void split_kernel(const float4* __restrict__ src,
                             __nv_bfloat16* __restrict__ hi,
                             __nv_bfloat16* __restrict__ lo, int n4) {
    int i = blockIdx.x * 256 + threadIdx.x;
    if (i >= n4) return;
    float4 v = src[i];
    split2(v.x, v.y, hi + i*4,     lo + i*4);
    split2(v.z, v.w, hi + i*4 + 2, lo + i*4 + 2);
}

// ---------------- embedding: x = emb[tgt]*32, also emit hi/lo ----------------
__global__ void embed_kernel(const int* __restrict__ tgt,
                             const float* __restrict__ emb,
                             float* __restrict__ x,
                             __nv_bfloat16* __restrict__ xh,
                             __nv_bfloat16* __restrict__ xl) {
    int idx = blockIdx.x * blockDim.x + threadIdx.x;
    int row = idx >> 8;
    int c4  = idx & 255;
    float4 v = reinterpret_cast<const float4*>(emb + (size_t)tgt[row] * ND)[c4];
    v.x *= 32.f; v.y *= 32.f; v.z *= 32.f; v.w *= 32.f;
    reinterpret_cast<float4*>(x)[idx] = v;
    split2(v.x, v.y, xh + idx*4,     xl + idx*4);
    split2(v.z, v.w, xh + idx*4 + 2, xl + idx*4 + 2);
}

// ---------------- split-K reduce: out = relu(alpha*(P0+P1+bias)), opt hi/lo ----------------
__global__ __launch_bounds__(256) void reduce2_kernel(
    float* __restrict__ out, __nv_bfloat16* __restrict__ oh, __nv_bfloat16* __restrict__ ol,
    const float* __restrict__ P, const float* __restrict__ bias,
    int N, int total4, float alpha, int relu)
{
    int idx = blockIdx.x * 256 + threadIdx.x;
    if (idx >= total4) return;
    const float4* P0 = reinterpret_cast<const float4*>(P);
    const float4* P1 = P0 + total4;
    float4 a = P0[idx], b = P1[idx];
    int col = (idx << 2) & (N - 1);
    float4 bz = *reinterpret_cast<const float4*>(bias + col);
    float4 o;
    o.x = (a.x + b.x + bz.x) * alpha;
    o.y = (a.y + b.y + bz.y) * alpha;
    o.z = (a.z + b.z + bz.z) * alpha;
    o.w = (a.w + b.w + bz.w) * alpha;
    if (relu) {
        o.x = fmaxf(o.x, 0.f); o.y = fmaxf(o.y, 0.f);
        o.z = fmaxf(o.z, 0.f); o.w = fmaxf(o.w, 0.f);
    }
    reinterpret_cast<float4*>(out)[idx] = o;
    if (oh) {
        split2(o.x, o.y, oh + idx*4,     ol + idx*4);
        split2(o.z, o.w, oh + idx*4 + 2, ol + idx*4 + 2);
    }
}

// ---------------- split-bf16 tensor-core GEMM (mma.sync) ----------------
// 8 warps (2x4), CTA tile 128x128, k-tile 32, 3-stage cp.async pipeline.
// Outputs: fp32 C, and/or bf16 hi/lo (Ch,Cl), or bf16 hi-only (Ch set, Cl null).
#define STG 32768
#define TOFF 8192
#define GEMM_SMEM (3*STG)

__device__ __forceinline__ void ld_tile_async(
    uint32_t sbase, const __nv_bfloat16* __restrict__ g,
    int ldk, int row0, int k0, int rmax, int tid)
{
    #pragma unroll
    for (int it = 0; it < 2; it++) {
        int qq = tid + it * 256;
        int r = qq >> 2, c = qq & 3;
        uint32_t dst = sbase + r * 64 + ((c ^ ((r >> 1) & 3)) << 4);
        int rr = (r < rmax) ? r : 0;
        const __nv_bfloat16* src = g + (size_t)(row0 + rr) * ldk + k0 + c * 8;
        int sz = (r < rmax) ? 16 : 0;
        CP_ASYNC16(dst, src, sz);
    }
}

__device__ __forceinline__ void ld_stage(
    uint32_t sbase, const __nv_bfloat16* Ah, const __nv_bfloat16* Al,
    const __nv_bfloat16* Bh, const __nv_bfloat16* Bl,
    int ldk, int m0, int n0, int k0, int bn, int tid, int terms)
{
    ld_tile_async(sbase + 0*TOFF, Ah, ldk, m0, k0, 128, tid);
    ld_tile_async(sbase + 2*TOFF, Bh, ldk, n0, k0, bn, tid);
    if (terms == 3) {
        ld_tile_async(sbase + 1*TOFF, Al, ldk, m0, k0, 128, tid);
        ld_tile_async(sbase + 3*TOFF, Bl, ldk, n0, k0, bn, tid);
    }
}

__global__ __launch_bounds__(256, 2) void gemm_tc(
    float* __restrict__ C, __nv_bfloat16* __restrict__ Ch, __nv_bfloat16* __restrict__ Cl,
    const __nv_bfloat16* __restrict__ Ah, const __nv_bfloat16* __restrict__ Al,
    const __nv_bfloat16* __restrict__ Bh, const __nv_bfloat16* __restrict__ Bl,
    const float* __restrict__ bias, int M, int N, int K, int ldk,
    float alpha, int relu, int terms)
{
    extern __shared__ char sm[];
    uint32_t smb = smem_u32(sm);
    int tid = threadIdx.x;
    int wid = tid >> 5;
    int lane = tid & 31;
    int wm = wid & 1;
    int wn = wid >> 1;
    int m0 = blockIdx.y * 128;
    int n0 = blockIdx.x * 128;
    int kbase = blockIdx.z * K;
    if (C) C += (size_t)blockIdx.z * M * N;
    int NT = K >> 5;
    int bn = N - n0; if (bn > 128) bn = 128;

    ld_stage(smb, Ah, Al, Bh, Bl, ldk, m0, n0, kbase, bn, tid, terms);
    CP_COMMIT();
    if (NT > 1) {
        ld_stage(smb + STG, Ah, Al, Bh, Bl, ldk, m0, n0, kbase + 32, bn, tid, terms);
        CP_COMMIT();
    }

    float acc[4][4][4];
    #pragma unroll
    for (int i = 0; i < 4; i++)
        #pragma unroll
        for (int j = 0; j < 4; j++)
            #pragma unroll
            for (int e = 0; e < 4; e++) acc[i][j][e] = 0.f;

    int slot = 0, pslot = 2;
    for (int kt = 0; kt < NT; kt++) {
        if (kt + 1 < NT) { CP_WAIT1(); } else { CP_WAIT0(); }
        __syncthreads();

        if (kt + 2 < NT) {
            ld_stage(smb + pslot * STG, Ah, Al, Bh, Bl, ldk, m0, n0,
                     kbase + ((kt + 2) << 5), bn, tid, terms);
            CP_COMMIT();
        }

        uint32_t sA = smb + slot * STG;
        uint32_t sB = sA + 2*TOFF;

        #pragma unroll
        for (int ks = 0; ks < 2; ks++) {
            uint32_t ah[4][4], al[4][4], bh[4][2], bl[4][2];
            #pragma unroll
            for (int mf = 0; mf < 4; mf++) {
                int row = wm * 64 + mf * 16 + (lane & 15);
                int cc = ks * 2 + (lane >> 4);
                uint32_t ad = sA + row * 64 + (((cc ^ ((row >> 1) & 3))) << 4);
                LDSM4(ah[mf], ad);
                if (terms == 3) LDSM4(al[mf], ad + TOFF);
            }
            #pragma unroll
            for (int nf = 0; nf < 4; nf++) {
                int rn = wn * 32 + nf * 8 + (lane & 7);
                int cc = ks * 2 + ((lane >> 3) & 1);
                uint32_t bd = sB + rn * 64 + (((cc ^ ((rn >> 1) & 3))) << 4);
                LDSM2(bh[nf], bd);
                if (terms == 3) LDSM2(bl[nf], bd + TOFF);
            }
            #pragma unroll
            for (int mf = 0; mf < 4; mf++)
                #pragma unroll
                for (int nf = 0; nf < 4; nf++)
                    MMA16816(acc[mf][nf], ah[mf], bh[nf]);
            if (terms == 3) {
                #pragma unroll
                for (int mf = 0; mf < 4; mf++)
                    #pragma unroll
                    for (int nf = 0; nf < 4; nf++)
                        MMA16816(acc[mf][nf], ah[mf], bl[nf]);
                #pragma unroll
                for (int mf = 0; mf < 4; mf++)
                    #pragma unroll
                    for (int nf = 0; nf < 4; nf++)
                        MMA16816(acc[mf][nf], al[mf], bh[nf]);
            }
        }
        slot = (slot == 2) ? 0 : slot + 1;
        pslot = (pslot == 2) ? 0 : pslot + 1;
    }

    // epilogue
    bool fast = ((N & 1) == 0) && (n0 + 128 <= N);
    #pragma unroll
    for (int mf = 0; mf < 4; mf++) {
        int r0 = m0 + wm * 64 + mf * 16 + (lane >> 2);
        #pragma unroll
        for (int half = 0; half < 2; half++) {
            int row = r0 + half * 8;
            size_t rbase = (size_t)row * N;
            #pragma unroll
            for (int nf = 0; nf < 4; nf++) {
                int col = n0 + wn * 32 + nf * 8 + (lane & 3) * 2;
                float v0 = acc[mf][nf][half * 2 + 0];
                float v1 = acc[mf][nf][half * 2 + 1];
                if (bias) { v0 += bias[col]; v1 += __ldg(&bias[col + 1]); }
                v0 *= alpha; v1 *= alpha;
                if (relu) { v0 = fmaxf(v0, 0.f); v1 = fmaxf(v1, 0.f); }
                if (fast) {
                    if (C) *reinterpret_cast<float2*>(C + rbase + col) = make_float2(v0, v1);
                    if (Ch) {
                        if (Cl) split2(v0, v1, Ch + rbase + col, Cl + rbase + col);
                        else *reinterpret_cast<__nv_bfloat162*>(Ch + rbase + col) =
                                 __nv_bfloat162(__float2bfloat16(v0), __float2bfloat16(v1));
                    }
                } else {
                    if (C) {
                        if (col < N)     C[rbase + col] = v0;
                        if (col + 1 < N) C[rbase + col + 1] = v1;
                    }
                    if (Ch && !Cl) {
                        if (col < N)     Ch[rbase + col] = __float2bfloat16(v0);
                        if (col + 1 < N) Ch[rbase + col + 1] = __float2bfloat16(v1);
                    }
                }
            }
        }
    }
}

// ---------------- fused attention (flash-style, exact softmax semantics) ----------------
// qr read as bf16; exp+AV fused (no ps stash); writes o as bf16 hi/lo.
#define QT 128
#define KT 64
#define LDQ 68

__global__ __launch_bounds__(128, 2) void attn_kernel(
    __nv_bfloat16* __restrict__ oh, __nv_bfloat16* __restrict__ ol,
    const float* __restrict__ q, const float* __restrict__ k,
    const float* __restrict__ v, const __nv_bfloat16* __restrict__ qrb,
    const int* __restrict__ tgt)
{
    extern __shared__ float smf[];
    float* qs = smf;
    float* ks = qs + QT*LDQ;
    float* vs = ks + KT*LDQ;
    int*   pf = (int*)(vs + KT*LDQ);

    int b = blockIdx.z, h = blockIdx.y;
    int tid = threadIdx.x;
    int i0 = blockIdx.x * QT;
    int i  = i0 + tid;

    for (int t = tid; t < QT*NDH/4; t += 128) {
        int r  = t >> 4;
        int c4 = (t & 15) << 2;
        float4 va = *reinterpret_cast<const float4*>(
            &q[((size_t)(b*NS + i0 + r))*ND + h*NDH + c4]);
        *reinterpret_cast<float4*>(&qs[r*LDQ + c4]) = va;
    }

    float o[NDH];
    #pragma unroll
    for (int d = 0; d < NDH; d++) o[d] = 0.f;
    float m = -1e30f, l = 0.f;
    const __nv_bfloat16* qrrow = qrb + ((size_t)((b*NS + i)*NH + h)) * NR + (1023 - i);

    // causal tile skipping (bit-exact when key 0 is unmasked)
    int jend = (tgt[b*NS] == 0) ? NS : (i0 + QT);

    for (int j0 = 0; j0 < jend; j0 += KT) {
        __syncthreads();
        for (int t = tid; t < KT*NDH/4; t += 128) {
            int r  = t >> 4;
            int c4 = (t & 15) << 2;
            size_t g = ((size_t)(b*NS + j0 + r))*ND + h*NDH + c4;
            *reinterpret_cast<float4*>(&ks[r*LDQ + c4]) =
                *reinterpret_cast<const float4*>(&k[g]);
            *reinterpret_cast<float4*>(&vs[r*LDQ + c4]) =
                *reinterpret_cast<const float4*>(&v[g]);
        }
        if (tid < KT) pf[tid] = (tgt[b*NS + j0 + tid] == 0) ? 1 : 0;
        __syncthreads();

        float s[KT];
        #pragma unroll
        for (int j = 0; j < KT; j++) s[j] = 0.f;
        #pragma unroll 1
        for (int d = 0; d < NDH; d += 4) {
            float4 qd = *reinterpret_cast<const float4*>(&qs[tid*LDQ + d]);
            #pragma unroll
            for (int j = 0; j < KT; j++) {
                float4 kj = *reinterpret_cast<const float4*>(&ks[j*LDQ + d]);
                s[j] += qd.x*kj.x + qd.y*kj.y + qd.z*kj.z + qd.w*kj.w;
            }
        }
        float mt = m;
        #pragma unroll
        for (int j = 0; j < KT; j++) {
            int jj = j0 + j;
            float val = s[j] + __bfloat162float(qrrow[jj]);
            if (jj > i || pf[j]) val = -1e9f;
            s[j] = val;
            mt = fmaxf(mt, val);
        }
        float corr = __expf(m - mt);
        m = mt;
        l *= corr;
        #pragma unroll
        for (int d = 0; d < NDH; d++) o[d] *= corr;
        // fused exp + AV
        #pragma unroll 1
        for (int j = 0; j < KT; j++) {
            float p = __expf(s[j] - m);
            l += p;
            #pragma unroll
            for (int d = 0; d < NDH; d += 4) {
                float4 vj = *reinterpret_cast<const float4*>(&vs[j*LDQ + d]);
                o[d]   += p*vj.x;
                o[d+1] += p*vj.y;
                o[d+2] += p*vj.z;
                o[d+3] += p*vj.w;
            }
        }
    }
    float inv = 1.f / l;
    size_t base = ((size_t)(b*NS + i))*ND + h*NDH;
    #pragma unroll
    for (int d = 0; d < NDH; d += 2)
        split2(o[d]*inv, o[d+1]*inv, oh + base + d, ol + base + d);
}

// ---------------- residual add + LayerNorm (in place on x, also emit hi/lo) ----------------
__global__ __launch_bounds__(256) void add_ln_kernel(
    float* __restrict__ x, __nv_bfloat16* __restrict__ xh, __nv_bfloat16* __restrict__ xl,
    const float* __restrict__ y,
    const float* __restrict__ gw, const float* __restrict__ bw)
{
    __shared__ float buf[ND];
    __shared__ float red[33];
    int row = blockIdx.x;
    int tid = threadIdx.x;
    size_t base = (size_t)row * ND;

    float s = 0.f;
    for (int d = tid; d < ND; d += 256) {
        float t = x[base + d] + y[base + d];
        buf[d] = t;
        s += t;
    }
    #pragma unroll
    for (int off = 16; off; off >>= 1) s += __shfl_xor_sync(0xffffffffu, s, off);
    if ((tid & 31) == 0) red[tid >> 5] = s;
    __syncthreads();
    if (tid < 32) {
        float v2 = (tid < 8) ? red[tid] : 0.f;
        #pragma unroll
        for (int off = 4; off; off >>= 1) v2 += __shfl_xor_sync(0xffffffffu, v2, off);
        if (tid == 0) red[32] = v2;
    }
    __syncthreads();
    float mean = red[32] * (1.f/ND);

    float sv = 0.f;
    for (int d = tid; d < ND; d += 256) {
        float t = buf[d] - mean;
        sv += t*t;
    }
    #pragma unroll
    for (int off = 16; off; off >>= 1) sv += __shfl_xor_sync(0xffffffffu, sv, off);
    __syncthreads();
    if ((tid & 31) == 0) red[tid >> 5] = sv;
    __syncthreads();
    if (tid < 32) {
        float v2 = (tid < 8) ? red[tid] : 0.f;
        #pragma unroll
        for (int off = 4; off; off >>= 1) v2 += __shfl_xor_sync(0xffffffffu, v2, off);
        if (tid == 0) red[32] = v2;
    }
    __syncthreads();
    float inv = rsqrtf(red[32] * (1.f/ND) + 1e-5f);
    for (int d = tid*2; d < ND; d += 512) {
        float v0 = (buf[d]   - mean) * inv * gw[d]   + bw[d];
        float v1 = (buf[d+1] - mean) * inv * gw[d+1] + bw[d+1];
        x[base + d]   = v0;
        x[base + d+1] = v1;
        split2(v0, v1, xh + base + d, xl + base + d);
    }
}

// ---------------- host orchestration ----------------
static inline void split(const float* src, __nv_bfloat16* hi, __nv_bfloat16* lo, size_t n) {
    int n4 = (int)(n / 4);
    split_kernel<<<(n4 + 255) / 256, 256>>>(
        reinterpret_cast<const float4*>(src), hi, lo, n4);
}

extern "C" void kernel_launch(void* const* d_in, const int* in_sizes, int n_in,
                              void* d_out, int out_size)
{
    (void)in_sizes; (void)n_in; (void)out_size;
    const int*   tgt = (const int*)d_in[0];
    const float* emb = (const float*)d_in[1];
    const float* Wq  = (const float*)d_in[2];
    const float* bq  = (const float*)d_in[3];
    const float* Wk  = (const float*)d_in[4];
    const float* bk  = (const float*)d_in[5];
    const float* Wv  = (const float*)d_in[6];
    const float* bv  = (const float*)d_in[7];
    const float* Wo  = (const float*)d_in[8];
    const float* bo  = (const float*)d_in[9];
    const float* rel = (const float*)d_in[10];
    const float* W1  = (const float*)d_in[11];
    const float* b1  = (const float*)d_in[12];
    const float* W2  = (const float*)d_in[13];
    const float* b2  = (const float*)d_in[14];
    const float* g1  = (const float*)d_in[15];
    const float* be1 = (const float*)d_in[16];
    const float* g2  = (const float*)d_in[17];
    const float* be2 = (const float*)d_in[18];
    const float* Wf  = (const float*)d_in[19];
    const float* bf  = (const float*)d_in[20];
    float* logits = (float*)d_out;

    float *x_, *q_, *k_, *v_, *t_, *p_;
    __nv_bfloat16 *qrb, *xh, *xl, *qh, *ql, *oh, *ol, *hh, *hl, *Bh, *Bl;
    cudaGetSymbolAddress((void**)&x_,  g_x);
    cudaGetSymbolAddress((void**)&q_,  g_q);
    cudaGetSymbolAddress((void**)&k_,  g_k);
    cudaGetSymbolAddress((void**)&v_,  g_v);
    cudaGetSymbolAddress((void**)&t_,  g_t);
    cudaGetSymbolAddress((void**)&p_,  g_p);
    cudaGetSymbolAddress((void**)&qrb, g_qrb);
    cudaGetSymbolAddress((void**)&xh,  g_xh);
    cudaGetSymbolAddress((void**)&xl,  g_xl);
    cudaGetSymbolAddress((void**)&qh,  g_qh);
    cudaGetSymbolAddress((void**)&ql,  g_ql);
    cudaGetSymbolAddress((void**)&oh,  g_oh);
    cudaGetSymbolAddress((void**)&ol,  g_ol);
    cudaGetSymbolAddress((void**)&hh,  g_hh);
    cudaGetSymbolAddress((void**)&hl,  g_hl);
    cudaGetSymbolAddress((void**)&Bh,  g_Bh);
    cudaGetSymbolAddress((void**)&Bl,  g_Bl);

    int attn_smem = (QT*LDQ + KT*LDQ + KT*LDQ)*(int)sizeof(float) + KT*(int)sizeof(int);
    cudaFuncSetAttribute(attn_kernel, cudaFuncAttributeMaxDynamicSharedMemorySize, attn_smem);
    cudaFuncSetAttribute(gemm_tc, cudaFuncAttributeMaxDynamicSharedMemorySize, GEMM_SMEM);

    embed_kernel<<<NROWS*ND/4/256, 256>>>(tgt, emb, x_, xh, xl);

    const int RED4 = NROWS*ND/4;
    const dim3 gRED((RED4 + 255)/256);
    __nv_bfloat16* nb = nullptr;
    float* nf = nullptr;

    for (int l = 0; l < NL; l++) {
        const size_t WDD = (size_t)ND*ND;
        // q/k/v projections: split-K=2 (K=512 per slice, ldk=1024)
        split(Wq + l*WDD, Bh, Bl, WDD);
        gemm_tc<<<dim3(ND/128, NROWS/128, 2), 256, GEMM_SMEM>>>(
            p_, nb, nb, xh, xl, Bh, Bl, nf, NROWS, ND, 512, ND, 1.f, 0, 3);
        reduce2_kernel<<<gRED, 256>>>(q_, qh, ql, p_, bq + l*ND, ND, RED4, 0.125f, 0);
        split(Wk + l*WDD, Bh, Bl, WDD);
        gemm_tc<<<dim3(ND/128, NROWS/128, 2), 256, GEMM_SMEM>>>(
            p_, nb, nb, xh, xl, Bh, Bl, nf, NROWS, ND, 512, ND, 1.f, 0, 3);
        reduce2_kernel<<<gRED, 256>>>(k_, nb, nb, p_, bk + l*ND, ND, RED4, 1.f, 0);
        split(Wv + l*WDD, Bh, Bl, WDD);
        gemm_tc<<<dim3(ND/128, NROWS/128, 2), 256, GEMM_SMEM>>>(
            p_, nb, nb, xh, xl, Bh, Bl, nf, NROWS, ND, 512, ND, 1.f, 0, 3);
        reduce2_kernel<<<gRED, 256>>>(v_, nb, nb, p_, bv + l*ND, ND, RED4, 1.f, 0);

        // QR[bsh, r] = q . rel^T : single-term bf16, bf16 output (hi-only)
        split(rel + (size_t)l*NR*NDH, Bh, Bl, (size_t)NR*NDH);
        gemm_tc<<<dim3((NR + 127)/128, NROWS*NH/128), 256, GEMM_SMEM>>>(
            nf, qrb, nb, qh, ql, Bh, Bl, nf, NROWS*NH, NR, NDH, NDH, 1.f, 0, 1);

        attn_kernel<<<dim3(NS/QT, NH, NB), 128, attn_smem>>>(oh, ol, q_, k_, v_, qrb, tgt);

        // output projection (split-K=2) + LN (emits xh/xl)
        split(Wo + l*WDD, Bh, Bl, WDD);
        gemm_tc<<<dim3(ND/128, NROWS/128, 2), 256, GEMM_SMEM>>>(
            p_, nb, nb, oh, ol, Bh, Bl, nf, NROWS, ND, 512, ND, 1.f, 0, 3);
        reduce2_kernel<<<gRED, 256>>>(t_, nb, nb, p_, bo + l*ND, ND, RED4, 1.f, 0);
        add_ln_kernel<<<NROWS, 256>>>(x_, xh, xl, t_, g1 + l*ND, be1 + l*ND);

        // FFN1: write h directly as bf16 hi/lo
        split(W1 + (size_t)l*NDFF*ND, Bh, Bl, (size_t)NDFF*ND);
        gemm_tc<<<dim3(NDFF/128, NROWS/128), 256, GEMM_SMEM>>>(
            nf, hh, hl, xh, xl, Bh, Bl, b1 + l*NDFF, NROWS, NDFF, ND, ND, 1.f, 1, 3);
        // FFN2 (K=4096 -> split-K=2 of 2048)
        split(W2 + (size_t)l*ND*NDFF, Bh, Bl, (size_t)ND*NDFF);
        gemm_tc<<<dim3(ND/128, NROWS/128, 2), 256, GEMM_SMEM>>>(
            p_, nb, nb, hh, hl, Bh, Bl, nf, NROWS, ND, 2048, NDFF, 1.f, 0, 3);
        reduce2_kernel<<<gRED, 256>>>(t_, nb, nb, p_, b2 + l*ND, ND, RED4, 1.f, 0);
        add_ln_kernel<<<NROWS, 256>>>(x_, xh, xl, t_, g2 + l*ND, be2 + l*ND);
    }

    // final logits: M=2048, N=32000, K=1024
    split(Wf, Bh, Bl, (size_t)NV*ND);
    gemm_tc<<<dim3(NV/128, NROWS/128), 256, GEMM_SMEM>>>(
        logits, nb, nb, xh, xl, Bh, Bl, bf, NROWS, NV, ND, ND, 1.f, 0, 3);
}

// round 10
// speedup vs baseline: 1.1289x; 1.1178x over previous
#include <cuda_runtime.h>
#include <cuda_bf16.h>
#include <cstdint>
#include <math.h>

// ---------------- problem constants ----------------
#define NB 2
#define NS 1024
#define ND 1024
#define NH 16
#define NDH 64
#define NL 4
#define NDFF 4096
#define NV 32000
#define NR 2047              // 2*MAXLEN-1
#define NROWS (NB*NS)        // 2048

// ---------------- scratch (static device allocations) ----------------
__device__ float g_x[NROWS*ND];
__device__ float g_q[NROWS*ND];
__device__ float g_k[NROWS*ND];
__device__ float g_v[NROWS*ND];
__device__ float g_t[NROWS*ND];
__device__ float g_p[2*NROWS*ND];                     // split-K partials
__device__ __nv_bfloat16 g_qrb[(size_t)NROWS*NH*NR];  // qr in bf16

// split-bf16 activation buffers (hi/lo)
__device__ __nv_bfloat16 g_xh[NROWS*ND],  g_xl[NROWS*ND];
__device__ __nv_bfloat16 g_qh[NROWS*ND],  g_ql[NROWS*ND];
__device__ __nv_bfloat16 g_oh[NROWS*ND],  g_ol[NROWS*ND];
__device__ __nv_bfloat16 g_hh[NROWS*NDFF], g_hl[NROWS*NDFF];
// weight split buffers
__device__ __nv_bfloat16 g_Bh[(size_t)NV*ND];
__device__ __nv_bfloat16 g_Bl[(size_t)NV*ND];

// ---------------- helpers ----------------
__device__ __forceinline__ uint32_t smem_u32(const void* p) {
    uint32_t a;
    asm("{ .reg .u64 t; cvta.to.shared.u64 t, %1; cvt.u32.u64 %0, t; }" : "=r"(a) : "l"(p));
    return a;
}

#define LDSM4(r, a) \
    asm volatile("ldmatrix.sync.aligned.m8n8.x4.shared.b16 {%0,%1,%2,%3}, [%4];" \
        : "=r"((r)[0]), "=r"((r)[1]), "=r"((r)[2]), "=r"((r)[3]) : "r"(a))
#define LDSM2(r, a) \
    asm volatile("ldmatrix.sync.aligned.m8n8.x2.shared.b16 {%0,%1}, [%2];" \
        : "=r"((r)[0]), "=r"((r)[1]) : "r"(a))

#define MMA16816(d, a, b) \
    asm volatile("mma.sync.aligned.m16n8k16.row.col.f32.bf16.bf16.f32 " \
        "{%0,%1,%2,%3}, {%4,%5,%6,%7}, {%8,%9}, {%0,%1,%2,%3};" \
        : "+f"((d)[0]), "+f"((d)[1]), "+f"((d)[2]), "+f"((d)[3]) \
        : "r"((a)[0]), "r"((a)[1]), "r"((a)[2]), "r"((a)[3]), "r"((b)[0]), "r"((b)[1]))

#define CP_ASYNC16(dst, src, sz) \
    asm volatile("cp.async.cg.shared.global [%0], [%1], 16, %2;" \
        :: "r"(dst), "l"(src), "r"(sz))
#define CP_COMMIT() asm volatile("cp.async.commit_group;")
#define CP_WAIT0()  asm volatile("cp.async.wait_group 0;")
#define CP_WAIT1()  asm volatile("cp.async.wait_group 1;")

__device__ __forceinline__ void split2(float v0, float v1,
                                       __nv_bfloat16* hi, __nv_bfloat16* lo) {
    __nv_bfloat16 h0 = __float2bfloat16(v0);
    __nv_bfloat16 h1 = __float2bfloat16(v1);
    __nv_bfloat16 l0 = __float2bfloat16(v0 - __bfloat162float(h0));
    __nv_bfloat16 l1 = __float2bfloat16(v1 - __bfloat162float(h1));
    *reinterpret_cast<__nv_bfloat162*>(hi) = __nv_bfloat162(h0, h1);
    *reinterpret_cast<__nv_bfloat162*>(lo) = __nv_bfloat162(l0, l1);
}

// ---------------- fp32 -> bf16 hi/lo split (weights) ----------------
__global__ void split_kernel(const float4* __restrict__ src,
                             __nv_bfloat16* __restrict__ hi,
                             __nv_bfloat16* __restrict__ lo, int n4) {
    int i = blockIdx.x * 256 + threadIdx.x;
    if (i >= n4) return;
    float4 v = src[i];
    split2(v.x, v.y, hi + i*4,     lo + i*4);
    split2(v.z, v.w, hi + i*4 + 2, lo + i*4 + 2);
}

// ---------------- embedding: x = emb[tgt]*32, also emit hi/lo ----------------
__global__ void embed_kernel(const int* __restrict__ tgt,
                             const float* __restrict__ emb,
                             float* __restrict__ x,
                             __nv_bfloat16* __restrict__ xh,
                             __nv_bfloat16* __restrict__ xl) {
    int idx = blockIdx.x * blockDim.x + threadIdx.x;
    int row = idx >> 8;
    int c4  = idx & 255;
    float4 v = reinterpret_cast<const float4*>(emb + (size_t)tgt[row] * ND)[c4];
    v.x *= 32.f; v.y *= 32.f; v.z *= 32.f; v.w *= 32.f;
    reinterpret_cast<float4*>(x)[idx] = v;
    split2(v.x, v.y, xh + idx*4,     xl + idx*4);
    split2(v.z, v.w, xh + idx*4 + 2, xl + idx*4 + 2);
}

// ---------------- split-K reduce: out = relu(alpha*(P0+P1+bias)), opt hi/lo ----------------
__global__ __launch_bounds__(256) void reduce2_kernel(
    float* __restrict__ out, __nv_bfloat16* __restrict__ oh, __nv_bfloat16* __restrict__ ol,
    const float* __restrict__ P, const float* __restrict__ bias,
    int N, int total4, float alpha, int relu)
{
    int idx = blockIdx.x * 256 + threadIdx.x;
    if (idx >= total4) return;
    const float4* P0 = reinterpret_cast<const float4*>(P);
    const float4* P1 = P0 + total4;
    float4 a = P0[idx], b = P1[idx];
    int col = (idx << 2) & (N - 1);
    float4 bz = *reinterpret_cast<const float4*>(bias + col);
    float4 o;
    o.x = (a.x + b.x + bz.x) * alpha;
    o.y = (a.y + b.y + bz.y) * alpha;
    o.z = (a.z + b.z + bz.z) * alpha;
    o.w = (a.w + b.w + bz.w) * alpha;
    if (relu) {
        o.x = fmaxf(o.x, 0.f); o.y = fmaxf(o.y, 0.f);
        o.z = fmaxf(o.z, 0.f); o.w = fmaxf(o.w, 0.f);
    }
    reinterpret_cast<float4*>(out)[idx] = o;
    if (oh) {
        split2(o.x, o.y, oh + idx*4,     ol + idx*4);
        split2(o.z, o.w, oh + idx*4 + 2, ol + idx*4 + 2);
    }
}

// ---------------- split-bf16 tensor-core GEMM (mma.sync) ----------------
// 8 warps (2x4), CTA tile 128x128, k-tile 32, 3-stage cp.async pipeline.
// Outputs: fp32 C, and/or bf16 hi/lo (Ch,Cl), or bf16 hi-only (Ch set, Cl null).
#define STG 32768
#define TOFF 8192
#define GEMM_SMEM (3*STG)

__device__ __forceinline__ void ld_tile_async(
    uint32_t sbase, const __nv_bfloat16* __restrict__ g,
    int ldk, int row0, int k0, int rmax, int tid)
{
    #pragma unroll
    for (int it = 0; it < 2; it++) {
        int qq = tid + it * 256;
        int r = qq >> 2, c = qq & 3;
        uint32_t dst = sbase + r * 64 + ((c ^ ((r >> 1) & 3)) << 4);
        int rr = (r < rmax) ? r : 0;
        const __nv_bfloat16* src = g + (size_t)(row0 + rr) * ldk + k0 + c * 8;
        int sz = (r < rmax) ? 16 : 0;
        CP_ASYNC16(dst, src, sz);
    }
}

__device__ __forceinline__ void ld_stage(
    uint32_t sbase, const __nv_bfloat16* Ah, const __nv_bfloat16* Al,
    const __nv_bfloat16* Bh, const __nv_bfloat16* Bl,
    int ldk, int m0, int n0, int k0, int bn, int tid, int terms)
{
    ld_tile_async(sbase + 0*TOFF, Ah, ldk, m0, k0, 128, tid);
    ld_tile_async(sbase + 2*TOFF, Bh, ldk, n0, k0, bn, tid);
    if (terms == 3) {
        ld_tile_async(sbase + 1*TOFF, Al, ldk, m0, k0, 128, tid);
        ld_tile_async(sbase + 3*TOFF, Bl, ldk, n0, k0, bn, tid);
    }
}

__global__ __launch_bounds__(256, 2) void gemm_tc(
    float* __restrict__ C, __nv_bfloat16* __restrict__ Ch, __nv_bfloat16* __restrict__ Cl,
    const __nv_bfloat16* __restrict__ Ah, const __nv_bfloat16* __restrict__ Al,
    const __nv_bfloat16* __restrict__ Bh, const __nv_bfloat16* __restrict__ Bl,
    const float* __restrict__ bias, int M, int N, int K, int ldk,
    float alpha, int relu, int terms)
{
    extern __shared__ char sm[];
    uint32_t smb = smem_u32(sm);
    int tid = threadIdx.x;
    int wid = tid >> 5;
    int lane = tid & 31;
    int wm = wid & 1;
    int wn = wid >> 1;
    int m0 = blockIdx.y * 128;
    int n0 = blockIdx.x * 128;
    int kbase = blockIdx.z * K;
    if (C) C += (size_t)blockIdx.z * M * N;
    int NT = K >> 5;
    int bn = N - n0; if (bn > 128) bn = 128;

    ld_stage(smb, Ah, Al, Bh, Bl, ldk, m0, n0, kbase, bn, tid, terms);
    CP_COMMIT();
    if (NT > 1) {
        ld_stage(smb + STG, Ah, Al, Bh, Bl, ldk, m0, n0, kbase + 32, bn, tid, terms);
        CP_COMMIT();
    }

    float acc[4][4][4];
    #pragma unroll
    for (int i = 0; i < 4; i++)
        #pragma unroll
        for (int j = 0; j < 4; j++)
            #pragma unroll
            for (int e = 0; e < 4; e++) acc[i][j][e] = 0.f;

    int slot = 0, pslot = 2;
    for (int kt = 0; kt < NT; kt++) {
        if (kt + 1 < NT) { CP_WAIT1(); } else { CP_WAIT0(); }
        __syncthreads();

        if (kt + 2 < NT) {
            ld_stage(smb + pslot * STG, Ah, Al, Bh, Bl, ldk, m0, n0,
                     kbase + ((kt + 2) << 5), bn, tid, terms);
            CP_COMMIT();
        }

        uint32_t sA = smb + slot * STG;
        uint32_t sB = sA + 2*TOFF;

        #pragma unroll
        for (int ks = 0; ks < 2; ks++) {
            uint32_t ah[4][4], al[4][4], bh[4][2], bl[4][2];
            #pragma unroll
            for (int mf = 0; mf < 4; mf++) {
                int row = wm * 64 + mf * 16 + (lane & 15);
                int cc = ks * 2 + (lane >> 4);
                uint32_t ad = sA + row * 64 + (((cc ^ ((row >> 1) & 3))) << 4);
                LDSM4(ah[mf], ad);
                if (terms == 3) LDSM4(al[mf], ad + TOFF);
            }
            #pragma unroll
            for (int nf = 0; nf < 4; nf++) {
                int rn = wn * 32 + nf * 8 + (lane & 7);
                int cc = ks * 2 + ((lane >> 3) & 1);
                uint32_t bd = sB + rn * 64 + (((cc ^ ((rn >> 1) & 3))) << 4);
                LDSM2(bh[nf], bd);
                if (terms == 3) LDSM2(bl[nf], bd + TOFF);
            }
            #pragma unroll
            for (int mf = 0; mf < 4; mf++)
                #pragma unroll
                for (int nf = 0; nf < 4; nf++)
                    MMA16816(acc[mf][nf], ah[mf], bh[nf]);
            if (terms == 3) {
                #pragma unroll
                for (int mf = 0; mf < 4; mf++)
                    #pragma unroll
                    for (int nf = 0; nf < 4; nf++)
                        MMA16816(acc[mf][nf], ah[mf], bl[nf]);
                #pragma unroll
                for (int mf = 0; mf < 4; mf++)
                    #pragma unroll
                    for (int nf = 0; nf < 4; nf++)
                        MMA16816(acc[mf][nf], al[mf], bh[nf]);
            }
        }
        slot = (slot == 2) ? 0 : slot + 1;
        pslot = (pslot == 2) ? 0 : pslot + 1;
    }

    // epilogue
    bool fast = ((N & 1) == 0) && (n0 + 128 <= N);
    #pragma unroll
    for (int mf = 0; mf < 4; mf++) {
        int r0 = m0 + wm * 64 + mf * 16 + (lane >> 2);
        #pragma unroll
        for (int half = 0; half < 2; half++) {
            int row = r0 + half * 8;
            size_t rbase = (size_t)row * N;
            #pragma unroll
            for (int nf = 0; nf < 4; nf++) {
                int col = n0 + wn * 32 + nf * 8 + (lane & 3) * 2;
                float v0 = acc[mf][nf][half * 2 + 0];
                float v1 = acc[mf][nf][half * 2 + 1];
                if (bias) { v0 += bias[col]; v1 += __ldg(&bias[col + 1]); }
                v0 *= alpha; v1 *= alpha;
                if (relu) { v0 = fmaxf(v0, 0.f); v1 = fmaxf(v1, 0.f); }
                if (fast) {
                    if (C) *reinterpret_cast<float2*>(C + rbase + col) = make_float2(v0, v1);
                    if (Ch) {
                        if (Cl) split2(v0, v1, Ch + rbase + col, Cl + rbase + col);
                        else *reinterpret_cast<__nv_bfloat162*>(Ch + rbase + col) =
                                 __nv_bfloat162(__float2bfloat16(v0), __float2bfloat16(v1));
                    }
                } else {
                    if (C) {
                        if (col < N)     C[rbase + col] = v0;
                        if (col + 1 < N) C[rbase + col + 1] = v1;
                    }
                    if (Ch && !Cl) {
                        if (col < N)     Ch[rbase + col] = __float2bfloat16(v0);
                        if (col + 1 < N) Ch[rbase + col + 1] = __float2bfloat16(v1);
                    }
                }
            }
        }
    }
}

// ---------------- fused attention (flash-style, exact softmax semantics) ----------------
// ps-stash form (measured good in R6/R7); qr read as bf16; writes o as bf16 hi/lo.
#define QT 128
#define KT 64
#define LDQ 68

__global__ __launch_bounds__(128, 2) void attn_kernel(
    __nv_bfloat16* __restrict__ oh, __nv_bfloat16* __restrict__ ol,
    const float* __restrict__ q, const float* __restrict__ k,
    const float* __restrict__ v, const __nv_bfloat16* __restrict__ qrb,
    const int* __restrict__ tgt)
{
    extern __shared__ float smf[];
    float* qs = smf;
    float* ks = qs + QT*LDQ;
    float* vs = ks + KT*LDQ;
    float* ps = vs + KT*LDQ;
    int*   pf = (int*)(ps + QT*LDQ);

    int b = blockIdx.z, h = blockIdx.y;
    int tid = threadIdx.x;
    int i0 = blockIdx.x * QT;
    int i  = i0 + tid;

    for (int t = tid; t < QT*NDH/4; t += 128) {
        int r  = t >> 4;
        int c4 = (t & 15) << 2;
        float4 va = *reinterpret_cast<const float4*>(
            &q[((size_t)(b*NS + i0 + r))*ND + h*NDH + c4]);
        *reinterpret_cast<float4*>(&qs[r*LDQ + c4]) = va;
    }

    float o[NDH];
    #pragma unroll
    for (int d = 0; d < NDH; d++) o[d] = 0.f;
    float m = -1e30f, l = 0.f;
    const __nv_bfloat16* qrrow = qrb + ((size_t)((b*NS + i)*NH + h)) * NR + (1023 - i);

    // causal tile skipping (bit-exact when key 0 is unmasked)
    int jend = (tgt[b*NS] == 0) ? NS : (i0 + QT);

    for (int j0 = 0; j0 < jend; j0 += KT) {
        __syncthreads();
        for (int t = tid; t < KT*NDH/4; t += 128) {
            int r  = t >> 4;
            int c4 = (t & 15) << 2;
            size_t g = ((size_t)(b*NS + j0 + r))*ND + h*NDH + c4;
            *reinterpret_cast<float4*>(&ks[r*LDQ + c4]) =
                *reinterpret_cast<const float4*>(&k[g]);
            *reinterpret_cast<float4*>(&vs[r*LDQ + c4]) =
                *reinterpret_cast<const float4*>(&v[g]);
        }
        if (tid < KT) pf[tid] = (tgt[b*NS + j0 + tid] == 0) ? 1 : 0;
        __syncthreads();

        float s[KT];
        #pragma unroll
        for (int j = 0; j < KT; j++) s[j] = 0.f;
        #pragma unroll 1
        for (int d = 0; d < NDH; d += 4) {
            float4 qd = *reinterpret_cast<const float4*>(&qs[tid*LDQ + d]);
            #pragma unroll
            for (int j = 0; j < KT; j++) {
                float4 kj = *reinterpret_cast<const float4*>(&ks[j*LDQ + d]);
                s[j] += qd.x*kj.x + qd.y*kj.y + qd.z*kj.z + qd.w*kj.w;
            }
        }
        float mt = m;
        #pragma unroll
        for (int j = 0; j < KT; j++) {
            int jj = j0 + j;
            float val = s[j] + __bfloat162float(qrrow[jj]);
            if (jj > i || pf[j]) val = -1e9f;
            s[j] = val;
            mt = fmaxf(mt, val);
        }
        float corr = __expf(m - mt);
        m = mt;
        l *= corr;
        #pragma unroll
        for (int d = 0; d < NDH; d++) o[d] *= corr;
        #pragma unroll
        for (int j = 0; j < KT; j += 4) {
            float4 pv;
            pv.x = __expf(s[j]   - m);
            pv.y = __expf(s[j+1] - m);
            pv.z = __expf(s[j+2] - m);
            pv.w = __expf(s[j+3] - m);
            l += pv.x + pv.y + pv.z + pv.w;
            *reinterpret_cast<float4*>(&ps[tid*LDQ + j]) = pv;
        }
        #pragma unroll 1
        for (int j = 0; j < KT; j++) {
            float p = ps[tid*LDQ + j];
            #pragma unroll
            for (int d = 0; d < NDH; d += 4) {
                float4 vj = *reinterpret_cast<const float4*>(&vs[j*LDQ + d]);
                o[d]   += p*vj.x;
                o[d+1] += p*vj.y;
                o[d+2] += p*vj.z;
                o[d+3] += p*vj.w;
            }
        }
    }
    float inv = 1.f / l;
    size_t base = ((size_t)(b*NS + i))*ND + h*NDH;
    #pragma unroll
    for (int d = 0; d < NDH; d += 2)
        split2(o[d]*inv, o[d+1]*inv, oh + base + d, ol + base + d);
}

// ---------------- residual add + LayerNorm (in place on x, also emit hi/lo) ----------------
__global__ __launch_bounds__(256) void add_ln_kernel(
    float* __restrict__ x, __nv_bfloat16* __restrict__ xh, __nv_bfloat16* __restrict__ xl,
    const float* __restrict__ y,
    const float* __restrict__ gw, const float* __restrict__ bw)
{
    __shared__ float buf[ND];
    __shared__ float red[33];
    int row = blockIdx.x;
    int tid = threadIdx.x;
    size_t base = (size_t)row * ND;

    float s = 0.f;
    for (int d = tid; d < ND; d += 256) {
        float t = x[base + d] + y[base + d];
        buf[d] = t;
        s += t;
    }
    #pragma unroll
    for (int off = 16; off; off >>= 1) s += __shfl_xor_sync(0xffffffffu, s, off);
    if ((tid & 31) == 0) red[tid >> 5] = s;
    __syncthreads();
    if (tid < 32) {
        float v2 = (tid < 8) ? red[tid] : 0.f;
        #pragma unroll
        for (int off = 4; off; off >>= 1) v2 += __shfl_xor_sync(0xffffffffu, v2, off);
        if (tid == 0) red[32] = v2;
    }
    __syncthreads();
    float mean = red[32] * (1.f/ND);

    float sv = 0.f;
    for (int d = tid; d < ND; d += 256) {
        float t = buf[d] - mean;
        sv += t*t;
    }
    #pragma unroll
    for (int off = 16; off; off >>= 1) sv += __shfl_xor_sync(0xffffffffu, sv, off);
    __syncthreads();
    if ((tid & 31) == 0) red[tid >> 5] = sv;
    __syncthreads();
    if (tid < 32) {
        float v2 = (tid < 8) ? red[tid] : 0.f;
        #pragma unroll
        for (int off = 4; off; off >>= 1) v2 += __shfl_xor_sync(0xffffffffu, v2, off);
        if (tid == 0) red[32] = v2;
    }
    __syncthreads();
    float inv = rsqrtf(red[32] * (1.f/ND) + 1e-5f);
    for (int d = tid*2; d < ND; d += 512) {
        float v0 = (buf[d]   - mean) * inv * gw[d]   + bw[d];
        float v1 = (buf[d+1] - mean) * inv * gw[d+1] + bw[d+1];
        x[base + d]   = v0;
        x[base + d+1] = v1;
        split2(v0, v1, xh + base + d, xl + base + d);
    }
}

// ---------------- host orchestration ----------------
static inline void split(const float* src, __nv_bfloat16* hi, __nv_bfloat16* lo, size_t n) {
    int n4 = (int)(n / 4);
    split_kernel<<<(n4 + 255) / 256, 256>>>(
        reinterpret_cast<const float4*>(src), hi, lo, n4);
}

extern "C" void kernel_launch(void* const* d_in, const int* in_sizes, int n_in,
                              void* d_out, int out_size)
{
    (void)in_sizes; (void)n_in; (void)out_size;
    const int*   tgt = (const int*)d_in[0];
    const float* emb = (const float*)d_in[1];
    const float* Wq  = (const float*)d_in[2];
    const float* bq  = (const float*)d_in[3];
    const float* Wk  = (const float*)d_in[4];
    const float* bk  = (const float*)d_in[5];
    const float* Wv  = (const float*)d_in[6];
    const float* bv  = (const float*)d_in[7];
    const float* Wo  = (const float*)d_in[8];
    const float* bo  = (const float*)d_in[9];
    const float* rel = (const float*)d_in[10];
    const float* W1  = (const float*)d_in[11];
    const float* b1  = (const float*)d_in[12];
    const float* W2  = (const float*)d_in[13];
    const float* b2  = (const float*)d_in[14];
    const float* g1  = (const float*)d_in[15];
    const float* be1 = (const float*)d_in[16];
    const float* g2  = (const float*)d_in[17];
    const float* be2 = (const float*)d_in[18];
    const float* Wf  = (const float*)d_in[19];
    const float* bf  = (const float*)d_in[20];
    float* logits = (float*)d_out;

    float *x_, *q_, *k_, *v_, *t_, *p_;
    __nv_bfloat16 *qrb, *xh, *xl, *qh, *ql, *oh, *ol, *hh, *hl, *Bh, *Bl;
    cudaGetSymbolAddress((void**)&x_,  g_x);
    cudaGetSymbolAddress((void**)&q_,  g_q);
    cudaGetSymbolAddress((void**)&k_,  g_k);
    cudaGetSymbolAddress((void**)&v_,  g_v);
    cudaGetSymbolAddress((void**)&t_,  g_t);
    cudaGetSymbolAddress((void**)&p_,  g_p);
    cudaGetSymbolAddress((void**)&qrb, g_qrb);
    cudaGetSymbolAddress((void**)&xh,  g_xh);
    cudaGetSymbolAddress((void**)&xl,  g_xl);
    cudaGetSymbolAddress((void**)&qh,  g_qh);
    cudaGetSymbolAddress((void**)&ql,  g_ql);
    cudaGetSymbolAddress((void**)&oh,  g_oh);
    cudaGetSymbolAddress((void**)&ol,  g_ol);
    cudaGetSymbolAddress((void**)&hh,  g_hh);
    cudaGetSymbolAddress((void**)&hl,  g_hl);
    cudaGetSymbolAddress((void**)&Bh,  g_Bh);
    cudaGetSymbolAddress((void**)&Bl,  g_Bl);

    int attn_smem = (QT*LDQ + KT*LDQ + KT*LDQ + QT*LDQ)*(int)sizeof(float) + KT*(int)sizeof(int);
    cudaFuncSetAttribute(attn_kernel, cudaFuncAttributeMaxDynamicSharedMemorySize, attn_smem);
    cudaFuncSetAttribute(gemm_tc, cudaFuncAttributeMaxDynamicSharedMemorySize, GEMM_SMEM);

    embed_kernel<<<NROWS*ND/4/256, 256>>>(tgt, emb, x_, xh, xl);

    const int RED4 = NROWS*ND/4;
    const dim3 gRED((RED4 + 255)/256);
    __nv_bfloat16* nb = nullptr;
    float* nf = nullptr;

    for (int l = 0; l < NL; l++) {
        const size_t WDD = (size_t)ND*ND;
        // q/k/v projections: split-K=2 (K=512 per slice, ldk=1024)
        split(Wq + l*WDD, Bh, Bl, WDD);
        gemm_tc<<<dim3(ND/128, NROWS/128, 2), 256, GEMM_SMEM>>>(
            p_, nb, nb, xh, xl, Bh, Bl, nf, NROWS, ND, 512, ND, 1.f, 0, 3);
        reduce2_kernel<<<gRED, 256>>>(q_, qh, ql, p_, bq + l*ND, ND, RED4, 0.125f, 0);
        split(Wk + l*WDD, Bh, Bl, WDD);
        gemm_tc<<<dim3(ND/128, NROWS/128, 2), 256, GEMM_SMEM>>>(
            p_, nb, nb, xh, xl, Bh, Bl, nf, NROWS, ND, 512, ND, 1.f, 0, 3);
        reduce2_kernel<<<gRED, 256>>>(k_, nb, nb, p_, bk + l*ND, ND, RED4, 1.f, 0);
        split(Wv + l*WDD, Bh, Bl, WDD);
        gemm_tc<<<dim3(ND/128, NROWS/128, 2), 256, GEMM_SMEM>>>(
            p_, nb, nb, xh, xl, Bh, Bl, nf, NROWS, ND, 512, ND, 1.f, 0, 3);
        reduce2_kernel<<<gRED, 256>>>(v_, nb, nb, p_, bv + l*ND, ND, RED4, 1.f, 0);

        // QR[bsh, r] = q . rel^T : single-term bf16, bf16 output (hi-only)
        split(rel + (size_t)l*NR*NDH, Bh, Bl, (size_t)NR*NDH);
        gemm_tc<<<dim3((NR + 127)/128, NROWS*NH/128), 256, GEMM_SMEM>>>(
            nf, qrb, nb, qh, ql, Bh, Bl, nf, NROWS*NH, NR, NDH, NDH, 1.f, 0, 1);

        attn_kernel<<<dim3(NS/QT, NH, NB), 128, attn_smem>>>(oh, ol, q_, k_, v_, qrb, tgt);

        // output projection (split-K=2) + LN (emits xh/xl)
        split(Wo + l*WDD, Bh, Bl, WDD);
        gemm_tc<<<dim3(ND/128, NROWS/128, 2), 256, GEMM_SMEM>>>(
            p_, nb, nb, oh, ol, Bh, Bl, nf, NROWS, ND, 512, ND, 1.f, 0, 3);
        reduce2_kernel<<<gRED, 256>>>(t_, nb, nb, p_, bo + l*ND, ND, RED4, 1.f, 0);
        add_ln_kernel<<<NROWS, 256>>>(x_, xh, xl, t_, g1 + l*ND, be1 + l*ND);

        // FFN1: write h directly as bf16 hi/lo
        split(W1 + (size_t)l*NDFF*ND, Bh, Bl, (size_t)NDFF*ND);
        gemm_tc<<<dim3(NDFF/128, NROWS/128), 256, GEMM_SMEM>>>(
            nf, hh, hl, xh, xl, Bh, Bl, b1 + l*NDFF, NROWS, NDFF, ND, ND, 1.f, 1, 3);
        // FFN2 (K=4096 -> split-K=2 of 2048)
        split(W2 + (size_t)l*ND*NDFF, Bh, Bl, (size_t)ND*NDFF);
        gemm_tc<<<dim3(ND/128, NROWS/128, 2), 256, GEMM_SMEM>>>(
            p_, nb, nb, hh, hl, Bh, Bl, nf, NROWS, ND, 2048, NDFF, 1.f, 0, 3);
        reduce2_kernel<<<gRED, 256>>>(t_, nb, nb, p_, b2 + l*ND, ND, RED4, 1.f, 0);
        add_ln_kernel<<<NROWS, 256>>>(x_, xh, xl, t_, g2 + l*ND, be2 + l*ND);
    }

    // final logits: M=2048, N=32000, K=1024
    split(Wf, Bh, Bl, (size_t)NV*ND);
    gemm_tc<<<dim3(NV/128, NROWS/128), 256, GEMM_SMEM>>>(
        logits, nb, nb, xh, xl, Bh, Bl, bf, NROWS, NV, ND, ND, 1.f, 0, 3);
}